// round 12
// baseline (speedup 1.0000x reference)
#include <cuda_runtime.h>
#include <cuda_fp16.h>
#include <math.h>
#include <stdint.h>

#define B 4096
#define H 512
#define H3 1536
#define L 41
#define V 128
#define BOS 2
#define KA 1024            /* A split: [Ah | Al] fp16 */
#define KW 1024            /* W split: [Wh | Wl] fp16 */
#define NCOMBO 1728        /* [gh 1536 | logits 128 | attn 41 pad-> 64] */

// ====================== device scratch ======================
__device__ __align__(128) float g_h[B * H];
__device__ __align__(128) float g_gh[B * H3];
__device__ __align__(128) float g_gi[B * H3];
__device__ __align__(128) float g_aw[B * 48];
__device__ __align__(128) float g_logits[B * V];
__device__ __align__(128) float g_encpad[L * H];
__device__ __align__(128) float g_PT[H * 48];
__device__ __align__(128) float g_enc_tab[V * H3];
__device__ __align__(128) float g_attn_tab[V * L];
__device__ __align__(128) float g_comb_tab[V * H];
__device__ __align__(128) float g_scores[B];
__device__ __align__(128) float g_combo_bias[NCOMBO];

__device__ __align__(128) __half g_hsplit[B * KA];
__device__ __align__(128) __half g_xsplit[B * KA];
__device__ __align__(128) __half g_w_enc[H3 * KW];
__device__ __align__(128) __half g_w_gi[H3 * KW];
__device__ __align__(128) __half g_w_combo[NCOMBO * KW];

// ====================== asm helpers ======================
__device__ __forceinline__ uint32_t smem_u32(const void* p) {
    uint32_t a;
    asm("{ .reg .u64 t; cvta.to.shared.u64 t, %1; cvt.u32.u64 %0, t; }" : "=r"(a) : "l"(p));
    return a;
}
__device__ __forceinline__ void cp16(uint32_t s, const void* g) {
    asm volatile("cp.async.cg.shared.global [%0], [%1], 16;" :: "r"(s), "l"(g));
}
#define CP_COMMIT() asm volatile("cp.async.commit_group;" ::: "memory")
#define CP_WAIT1()  asm volatile("cp.async.wait_group 1;" ::: "memory")
#define CP_WAIT0()  asm volatile("cp.async.wait_group 0;" ::: "memory")
#define LDMX4(r0, r1, r2, r3, a) \
    asm volatile("ldmatrix.sync.aligned.m8n8.x4.shared.b16 {%0,%1,%2,%3}, [%4];" \
        : "=r"(r0), "=r"(r1), "=r"(r2), "=r"(r3) : "r"(a))
#define MMA16816(d, a, bb) \
    asm volatile("mma.sync.aligned.m16n8k16.row.col.f32.f16.f16.f32 " \
        "{%0,%1,%2,%3}, {%4,%5,%6,%7}, {%8,%9}, {%0,%1,%2,%3};" \
        : "+f"((d)[0]), "+f"((d)[1]), "+f"((d)[2]), "+f"((d)[3]) \
        : "r"((a)[0]), "r"((a)[1]), "r"((a)[2]), "r"((a)[3]), \
          "r"((bb)[0]), "r"((bb)[1]))

// ====================== fp16 3-segment HMMA GEMM (big warp tiles + K-split) ======================
// C = Ah*Wh + Ah*Wl + Al*Wh  (drops only Al*Wl ~2^-24), fp32 accum.
// BM=128, BN=64, 256 threads: warps = 2m x 2n x 2k, warp tile 64x32.
// Each k-group accumulates half the k16 steps; reduced once via smem.
// 8 K-chunks of 64 (PITCH=144), double-buffered cp.async, 2 CTAs/SM.
// mode 0: C0[m*N+n] = acc + bias[n]
// mode 1 (combo, bn = (blockIdx.x+tileOff)*64):
//   bn<1536       : gh -> C0 (ld 1536, +bias)
//   1536<=bn<1664 : logits -> C2 (ld 128, +bias)
//   bn==1664      : attn(41) -> fused softmax (incl attn_tab[tok]) -> awOut [B,48]
#define PITCH 144
#define OFF_WL (64 * PITCH)            /* 9216 */
#define OFF_AH (2 * 64 * PITCH)        /* 18432 */
#define OFF_AL (OFF_AH + 128 * PITCH)  /* 36864 */
#define STAGE (OFF_AL + 128 * PITCH)   /* 55296 */
#define SMEM_F16 (2 * STAGE)           /* 110592 -> 2 CTAs/SM */

__global__ void __launch_bounds__(256, 2) gemm_f16(
    int N,
    const __half* __restrict__ A,
    const __half* __restrict__ W,
    int mode,
    float* __restrict__ C0,
    float* __restrict__ C2,
    const float* __restrict__ bias,
    const float* __restrict__ attn_tab,
    const int* __restrict__ tgt,
    float* __restrict__ awOut,
    int tileOff)
{
    extern __shared__ __align__(128) char smem[];
    const uint32_t sb = smem_u32(smem);
    const int tid = threadIdx.x;
    const int lane = tid & 31;
    const int wid = tid >> 5;
    const int kg = wid >> 2;          // 0/1 k-group
    const int wm = (wid >> 1) & 1;    // 0/1 -> 64 rows
    const int wn = wid & 1;           // 0/1 -> 32 cols
    const int bm = blockIdx.y * 128;
    const int bn = (blockIdx.x + tileOff) * 64;

    auto load_tile = [&](int c) {
        const uint32_t st = sb + (c & 1) * STAGE;
        const size_t koff = (size_t)c * 64;
#pragma unroll
        for (int i = 0; i < 2; i++) {
            int idx = tid + i * 256;           // 0..511 -> 64 rows x 8 cols
            int row = idx >> 3, col = idx & 7;
            const __half* wr = W + (size_t)(bn + row) * KW + koff + col * 8;
            cp16(st + row * PITCH + col * 16, wr);                 // Wh
            cp16(st + OFF_WL + row * PITCH + col * 16, wr + 512);  // Wl
        }
#pragma unroll
        for (int i = 0; i < 4; i++) {
            int idx = tid + i * 256;           // 0..1023 -> 128 rows x 8 cols
            int row = idx >> 3, col = idx & 7;
            const __half* ar = A + (size_t)(bm + row) * KA + koff + col * 8;
            cp16(st + OFF_AH + row * PITCH + col * 16, ar);        // Ah
            cp16(st + OFF_AL + row * PITCH + col * 16, ar + 512);  // Al
        }
        CP_COMMIT();
    };

    float acc[4][4][4];
#pragma unroll
    for (int i = 0; i < 4; i++)
#pragma unroll
        for (int j = 0; j < 4; j++)
#pragma unroll
            for (int k = 0; k < 4; k++) acc[i][j][k] = 0.f;

    const uint32_t rowsel = lane & 15;
    const uint32_t khalf = (uint32_t)(lane >> 4);

    load_tile(0);
    load_tile(1);
    for (int c = 0; c < 8; c++) {
        if (c < 7) { CP_WAIT1(); }
        else       { CP_WAIT0(); }
        __syncthreads();

        const uint32_t st = sb + (c & 1) * STAGE;
        const uint32_t sWh = st + (wn * 32) * PITCH;
        const uint32_t sWl = st + OFF_WL + (wn * 32) * PITCH;
        const uint32_t sAh = st + OFF_AH + (wm * 64) * PITCH;
        const uint32_t sAl = st + OFF_AL + (wm * 64) * PITCH;
#pragma unroll
        for (int kl = 0; kl < 2; kl++) {
            const uint32_t kb = (uint32_t)(kg * 2 + kl) * 32 + khalf * 16;
            // bh
            uint32_t bh[4][2];
#pragma unroll
            for (int np = 0; np < 2; np++) {
                uint32_t r0, r1, r2, r3;
                LDMX4(r0, r1, r2, r3, sWh + (np * 16 + rowsel) * PITCH + kb);
                bh[np * 2][0] = r0; bh[np * 2 + 1][0] = r1;
                bh[np * 2][1] = r2; bh[np * 2 + 1][1] = r3;
            }
            // ah ; ah*bh
            uint32_t ah[4][4];
#pragma unroll
            for (int mi = 0; mi < 4; mi++)
                LDMX4(ah[mi][0], ah[mi][1], ah[mi][2], ah[mi][3],
                      sAh + (mi * 16 + rowsel) * PITCH + kb);
#pragma unroll
            for (int mi = 0; mi < 4; mi++)
#pragma unroll
                for (int ni = 0; ni < 4; ni++)
                    MMA16816(acc[mi][ni], ah[mi], bh[ni]);
            // al ; al*bh
            uint32_t al[4][4];
#pragma unroll
            for (int mi = 0; mi < 4; mi++)
                LDMX4(al[mi][0], al[mi][1], al[mi][2], al[mi][3],
                      sAl + (mi * 16 + rowsel) * PITCH + kb);
#pragma unroll
            for (int mi = 0; mi < 4; mi++)
#pragma unroll
                for (int ni = 0; ni < 4; ni++)
                    MMA16816(acc[mi][ni], al[mi], bh[ni]);
            // bl ; ah*bl
            uint32_t bl[4][2];
#pragma unroll
            for (int np = 0; np < 2; np++) {
                uint32_t r0, r1, r2, r3;
                LDMX4(r0, r1, r2, r3, sWl + (np * 16 + rowsel) * PITCH + kb);
                bl[np * 2][0] = r0; bl[np * 2 + 1][0] = r1;
                bl[np * 2][1] = r2; bl[np * 2 + 1][1] = r3;
            }
#pragma unroll
            for (int mi = 0; mi < 4; mi++)
#pragma unroll
                for (int ni = 0; ni < 4; ni++)
                    MMA16816(acc[mi][ni], ah[mi], bl[ni]);
        }
        __syncthreads();
        if (c + 2 < 8) load_tile(c + 2);
    }

    // ---- K-split reduction: kg1 -> smem, kg0 adds ----
    const int qr = lane >> 2;
    const int qc = (lane & 3) * 2;
    float* red = reinterpret_cast<float*>(smem);   // [128][64]
    if (kg == 1) {
#pragma unroll
        for (int mi = 0; mi < 4; mi++) {
            const int r0 = wm * 64 + mi * 16 + qr;
#pragma unroll
            for (int ni = 0; ni < 4; ni++) {
                const int c0 = wn * 32 + ni * 8 + qc;
                float* a4 = acc[mi][ni];
                red[r0 * 64 + c0]           = a4[0];
                red[r0 * 64 + c0 + 1]       = a4[1];
                red[(r0 + 8) * 64 + c0]     = a4[2];
                red[(r0 + 8) * 64 + c0 + 1] = a4[3];
            }
        }
    }
    __syncthreads();
    if (kg == 0) {
#pragma unroll
        for (int mi = 0; mi < 4; mi++) {
            const int r0 = wm * 64 + mi * 16 + qr;
#pragma unroll
            for (int ni = 0; ni < 4; ni++) {
                const int c0 = wn * 32 + ni * 8 + qc;
                float* a4 = acc[mi][ni];
                a4[0] += red[r0 * 64 + c0];
                a4[1] += red[r0 * 64 + c0 + 1];
                a4[2] += red[(r0 + 8) * 64 + c0];
                a4[3] += red[(r0 + 8) * 64 + c0 + 1];
            }
        }
    }

    // ---- epilogue (kg0 warps = tid < 128 hold final results) ----
    const bool fusedAttn = (mode == 1) && (bn == 1664);

    if (!fusedAttn) {
        if (kg == 0) {
#pragma unroll
            for (int mi = 0; mi < 4; mi++) {
                const size_t m0 = (size_t)(bm + wm * 64 + mi * 16 + qr);
#pragma unroll
                for (int ni = 0; ni < 4; ni++) {
                    const int n0 = bn + wn * 32 + ni * 8 + qc;
                    float* a4 = acc[mi][ni];
                    float v0 = a4[0] + bias[n0];
                    float v1 = a4[1] + bias[n0 + 1];
                    float v2 = a4[2] + bias[n0];
                    float v3 = a4[3] + bias[n0 + 1];
                    if (mode == 0) {
                        C0[m0 * N + n0]           = v0;
                        C0[m0 * N + n0 + 1]       = v1;
                        C0[(m0 + 8) * N + n0]     = v2;
                        C0[(m0 + 8) * N + n0 + 1] = v3;
                    } else if (n0 < 1536) {
                        C0[m0 * 1536 + n0]           = v0;
                        C0[m0 * 1536 + n0 + 1]       = v1;
                        C0[(m0 + 8) * 1536 + n0]     = v2;
                        C0[(m0 + 8) * 1536 + n0 + 1] = v3;
                    } else {
                        const int nl = n0 - 1536;
                        C2[m0 * 128 + nl]           = v0;
                        C2[m0 * 128 + nl + 1]       = v1;
                        C2[(m0 + 8) * 128 + nl]     = v2;
                        C2[(m0 + 8) * 128 + nl + 1] = v3;
                    }
                }
            }
        }
        return;
    }

    // fused attention softmax over 128 rows x 41 cols
    __syncthreads();
    float* ep = reinterpret_cast<float*>(smem);   // [128][49]
    if (kg == 0) {
#pragma unroll
        for (int mi = 0; mi < 4; mi++) {
            const int r0 = wm * 64 + mi * 16 + qr;
#pragma unroll
            for (int ni = 0; ni < 4; ni++) {
                const int c0 = wn * 32 + ni * 8 + qc;
                float* a4 = acc[mi][ni];
#pragma unroll
                for (int e = 0; e < 4; e++) {
                    const int r = r0 + ((e >= 2) ? 8 : 0);
                    const int cc = c0 + (e & 1);
                    if (cc < 41) ep[r * 49 + cc] = a4[e] + bias[bn + cc];
                }
            }
        }
    }
    __syncthreads();

    if (tid < 128) {
        const size_t m = (size_t)(bm + tid);
        int tk = tgt ? tgt[m] : BOS;
        const float* tb = attn_tab + (size_t)tk * L;
        float* row = ep + tid * 49;
        float mx = -1e30f;
        for (int l = 0; l < L; l++) {
            float v = row[l] + tb[l];
            row[l] = v;
            mx = fmaxf(mx, v);
        }
        float s = 0.f;
        for (int l = 0; l < L; l++) {
            float e = __expf(row[l] - mx);
            row[l] = e;
            s += e;
        }
        float inv = 1.f / s;
        for (int l = 0; l < L; l++) row[l] *= inv;
        for (int l = L; l < 48; l++) row[l] = 0.f;
    }
    __syncthreads();
    for (int i = tid; i < 128 * 48; i += 256) {
        int r = i / 48, c = i - r * 48;
        awOut[(size_t)(bm + r) * 48 + c] = ep[r * 49 + c];
    }
}

// ====================== fp32 SIMT GEMM (prep tables + PT) ======================
__global__ void __launch_bounds__(256) gemm_nt(
    int M, int N, int K,
    const float* __restrict__ A, int lda,
    const float* __restrict__ W, int ldw,
    float* __restrict__ C, int ldc,
    const float* __restrict__ bias)
{
    __shared__ float As[16][128];
    __shared__ float Ws[16][64];
    const int bm = blockIdx.y * 128;
    const int bn = blockIdx.x * 64;
    const int tid = threadIdx.x;
    const int tx = tid & 15;
    const int ty = tid >> 4;

    float acc[8][4];
#pragma unroll
    for (int i = 0; i < 8; i++)
#pragma unroll
        for (int j = 0; j < 4; j++) acc[i][j] = 0.f;

    for (int k0 = 0; k0 < K; k0 += 16) {
#pragma unroll
        for (int i = 0; i < 2; i++) {
            int flat = tid + i * 256;
            int r = flat >> 2;
            int c4 = (flat & 3) << 2;
            float4 v = *reinterpret_cast<const float4*>(A + (size_t)(bm + r) * lda + k0 + c4);
            As[c4 + 0][r] = v.x; As[c4 + 1][r] = v.y;
            As[c4 + 2][r] = v.z; As[c4 + 3][r] = v.w;
        }
        {
            int r = tid >> 2;
            int c4 = (tid & 3) << 2;
            float4 v = make_float4(0.f, 0.f, 0.f, 0.f);
            if (bn + r < N)
                v = *reinterpret_cast<const float4*>(W + (size_t)(bn + r) * ldw + k0 + c4);
            Ws[c4 + 0][r] = v.x; Ws[c4 + 1][r] = v.y;
            Ws[c4 + 2][r] = v.z; Ws[c4 + 3][r] = v.w;
        }
        __syncthreads();
#pragma unroll
        for (int k = 0; k < 16; k++) {
            float4 a0 = *reinterpret_cast<const float4*>(&As[k][ty * 8]);
            float4 a1 = *reinterpret_cast<const float4*>(&As[k][ty * 8 + 4]);
            float4 w0 = *reinterpret_cast<const float4*>(&Ws[k][tx * 4]);
            float a[8] = {a0.x, a0.y, a0.z, a0.w, a1.x, a1.y, a1.z, a1.w};
            float w[4] = {w0.x, w0.y, w0.z, w0.w};
#pragma unroll
            for (int i = 0; i < 8; i++)
#pragma unroll
                for (int j = 0; j < 4; j++) acc[i][j] += a[i] * w[j];
        }
        __syncthreads();
    }

#pragma unroll
    for (int i = 0; i < 8; i++) {
        size_t m = (size_t)(bm + ty * 8 + i);
#pragma unroll
        for (int j = 0; j < 4; j++) {
            int n = bn + tx * 4 + j;
            if (n < N) {
                float v = acc[i][j];
                if (bias) v += bias[n];
                C[m * ldc + n] = v;
            }
        }
    }
}

// ====================== elementwise / fused small kernels ======================
__device__ __forceinline__ float sigmoidf_(float x) {
    return __fdividef(1.f, 1.f + __expf(-x));
}
__device__ __forceinline__ float tanhf_(float x) {
    return 1.f - __fdividef(2.f, __expf(2.f * x) + 1.f);
}

__global__ void gru_gates(const float* __restrict__ gi,
                          const float* __restrict__ giTab,
                          const int* __restrict__ tokRow,
                          const float* __restrict__ gh,
                          float* __restrict__ h,
                          __half2* __restrict__ hsplit,
                          float* __restrict__ encRow)
{
    int i = blockIdx.x * blockDim.x + threadIdx.x;   // < B*H/2
    int b = i >> 8;
    int j = (i & 255) << 1;
    const float* p;
    if (giTab) p = giTab + (size_t)tokRow[b] * H3;
    else       p = gi + (size_t)b * H3;
    float2 gir = *reinterpret_cast<const float2*>(p + j);
    float2 giz = *reinterpret_cast<const float2*>(p + H + j);
    float2 gin = *reinterpret_cast<const float2*>(p + 2 * H + j);
    const float* q = gh + (size_t)b * H3;
    float2 qr = *reinterpret_cast<const float2*>(q + j);
    float2 qz = *reinterpret_cast<const float2*>(q + H + j);
    float2 qn = *reinterpret_cast<const float2*>(q + 2 * H + j);
    float2 hv = *reinterpret_cast<const float2*>(h + (size_t)b * H + j);

    float r0 = sigmoidf_(gir.x + qr.x), r1 = sigmoidf_(gir.y + qr.y);
    float z0 = sigmoidf_(giz.x + qz.x), z1 = sigmoidf_(giz.y + qz.y);
    float n0 = tanhf_(gin.x + r0 * qn.x), n1 = tanhf_(gin.y + r1 * qn.y);
    float h0 = (1.f - z0) * n0 + z0 * hv.x;
    float h1 = (1.f - z1) * n1 + z1 * hv.y;

    *reinterpret_cast<float2*>(h + (size_t)b * H + j) = make_float2(h0, h1);
    __half hh0 = __float2half_rn(h0), hh1 = __float2half_rn(h1);
    __half hl0 = __float2half_rn(h0 - __half2float(hh0));
    __half hl1 = __float2half_rn(h1 - __half2float(hh1));
    size_t base = ((size_t)b * KA + j) >> 1;
    hsplit[base] = __halves2half2(hh0, hh1);
    hsplit[base + 256] = __halves2half2(hl0, hl1);
    if (encRow && b == 0)
        *reinterpret_cast<float2*>(encRow + j) = make_float2(h0, h1);
}

// x = relu(comb_tab[tok] + aw @ PT^T) + fp16 split; K=48 fp32
#define SXP 132
#define SMEM_SX (2 * 48 * SXP * 4 + 128 * 4)
__global__ void __launch_bounds__(256) x_gemm(
    const float* __restrict__ aw,
    const int* __restrict__ tok, int defTok,
    const float* __restrict__ PT,
    const float* __restrict__ comb_tab,
    __half* __restrict__ xsplit)
{
    extern __shared__ __align__(16) char smraw[];
    float* awT = reinterpret_cast<float*>(smraw);
    float* PTt = awT + 48 * SXP;
    int* toks = reinterpret_cast<int*>(PTt + 48 * SXP);
    const int tid = threadIdx.x;
    const int rb = blockIdx.y * 128;
    const int nb = blockIdx.x * 128;

#pragma unroll
    for (int i = 0; i < 6; i++) {
        int idx = tid + i * 256;
        int row = idx / 12, c4 = idx % 12;
        float4 v = *reinterpret_cast<const float4*>(PT + (size_t)(nb + row) * 48 + c4 * 4);
        PTt[(c4 * 4 + 0) * SXP + row] = v.x;
        PTt[(c4 * 4 + 1) * SXP + row] = v.y;
        PTt[(c4 * 4 + 2) * SXP + row] = v.z;
        PTt[(c4 * 4 + 3) * SXP + row] = v.w;
        float4 u = *reinterpret_cast<const float4*>(aw + (size_t)(rb + row) * 48 + c4 * 4);
        awT[(c4 * 4 + 0) * SXP + row] = u.x;
        awT[(c4 * 4 + 1) * SXP + row] = u.y;
        awT[(c4 * 4 + 2) * SXP + row] = u.z;
        awT[(c4 * 4 + 3) * SXP + row] = u.w;
    }
    if (tid < 128) toks[tid] = tok ? tok[rb + tid] : defTok;
    __syncthreads();

    const int ty = tid >> 4;
    const int tx = tid & 15;
    float acc[8][8];
#pragma unroll
    for (int i = 0; i < 8; i++)
#pragma unroll
        for (int j = 0; j < 8; j++) acc[i][j] = 0.f;

    for (int k = 0; k < 48; k++) {
        float4 a0 = *reinterpret_cast<const float4*>(awT + k * SXP + ty * 8);
        float4 a1 = *reinterpret_cast<const float4*>(awT + k * SXP + ty * 8 + 4);
        float4 b0 = *reinterpret_cast<const float4*>(PTt + k * SXP + tx * 8);
        float4 b1 = *reinterpret_cast<const float4*>(PTt + k * SXP + tx * 8 + 4);
        float a[8] = {a0.x, a0.y, a0.z, a0.w, a1.x, a1.y, a1.z, a1.w};
        float bb[8] = {b0.x, b0.y, b0.z, b0.w, b1.x, b1.y, b1.z, b1.w};
#pragma unroll
        for (int i = 0; i < 8; i++)
#pragma unroll
            for (int j = 0; j < 8; j++) acc[i][j] += a[i] * bb[j];
    }

#pragma unroll
    for (int i = 0; i < 8; i++) {
        size_t m = (size_t)(rb + ty * 8 + i);
        const float* tb = comb_tab + (size_t)toks[ty * 8 + i] * 512;
#pragma unroll
        for (int j = 0; j < 8; j++) {
            int n = nb + tx * 8 + j;
            float v = fmaxf(acc[i][j] + tb[n], 0.f);
            __half hi = __float2half_rn(v);
            __half lo = __float2half_rn(v - __half2float(hi));
            xsplit[m * KA + n] = hi;
            xsplit[m * KA + 512 + n] = lo;
        }
    }
}

__global__ void out_gold(const float* __restrict__ logits,
                         const int* __restrict__ tgtRow,
                         float* __restrict__ scores)
{
    int warp = (blockIdx.x * blockDim.x + threadIdx.x) >> 5;
    int lane = threadIdx.x & 31;
    if (warp >= B) return;
    const float* row = logits + (size_t)warp * V;
    float v[4];
    float mx = -1e30f;
#pragma unroll
    for (int i = 0; i < 4; i++) { v[i] = row[lane + 32 * i]; mx = fmaxf(mx, v[i]); }
#pragma unroll
    for (int o = 16; o > 0; o >>= 1) mx = fmaxf(mx, __shfl_xor_sync(~0u, mx, o));
    float s = 0.f;
#pragma unroll
    for (int i = 0; i < 4; i++) s += __expf(v[i] - mx);
#pragma unroll
    for (int o = 16; o > 0; o >>= 1) s += __shfl_xor_sync(~0u, s, o);
    if (lane == 0) {
        int tgt = tgtRow[warp];
        if (tgt != 0) scores[warp] += row[tgt] - (mx + logf(s));
    }
}

__global__ void init_h(const float* __restrict__ h0)
{
    int i = blockIdx.x * blockDim.x + threadIdx.x;
    if (i >= B * H) return;
    float v = h0[i];
    g_h[i] = v;
    int b = i >> 9, j = i & 511;
    __half hi = __float2half_rn(v);
    __half lo = __float2half_rn(v - __half2float(hi));
    size_t base = (size_t)b * KA + j;
    g_hsplit[base] = hi; g_hsplit[base + 512] = lo;
    if (i < B) g_scores[i] = 0.f;
}

__global__ void split_w(__half* __restrict__ dst,
                        const float* __restrict__ src, int ldw, int colOff,
                        int rows, int dstRowOff)
{
    int i = blockIdx.x * blockDim.x + threadIdx.x;
    if (i >= rows * 512) return;
    int r = i >> 9, k = i & 511;
    float w = src[(size_t)r * ldw + colOff + k];
    __half hi = __float2half_rn(w);
    __half lo = __float2half_rn(w - __half2float(hi));
    size_t base = (size_t)(dstRowOff + r) * KW + k;
    dst[base] = hi; dst[base + 512] = lo;
}

__global__ void build_combo_bias(const float* __restrict__ bhh,
                                 const float* __restrict__ outb)
{
    int n = blockIdx.x * blockDim.x + threadIdx.x;
    if (n >= NCOMBO) return;
    g_combo_bias[n] = (n < 1536) ? bhh[n] : ((n < 1664) ? outb[n - 1536] : 0.f);
}

__global__ void scores_out(float* __restrict__ out)
{
    int i = blockIdx.x * blockDim.x + threadIdx.x;
    if (i < B) out[i] = g_scores[i];
}

__global__ void bcast_out(float* __restrict__ out)
{
    int idx = blockIdx.x * 256 + threadIdx.x;
    if (idx >= (L * H) / 4) return;
    int b = blockIdx.y;
    const float4* src = reinterpret_cast<const float4*>(g_encpad);
    float4* dst = reinterpret_cast<float4*>(out) + (B / 4) + (size_t)b * (L * H / 4);
    dst[idx] = src[idx];
}

// ====================== host ======================
static void launch_f16(dim3 grid, int N, const __half* A, const __half* W, int mode,
                       float* C0, float* C2, const float* bias,
                       const float* attn_tab, const int* tgt, float* awOut,
                       int tileOff)
{
    gemm_f16<<<grid, 256, SMEM_F16>>>(N, A, W, mode, C0, C2, bias, attn_tab,
                                      tgt, awOut, tileOff);
}

extern "C" void kernel_launch(void* const* d_in, const int* in_sizes, int n_in,
                              void* d_out, int out_size)
{
    const int*   input   = (const int*)  d_in[0];
    const float* enc_h0  = (const float*)d_in[1];
    const int*   target  = (const int*)  d_in[2];
    const float* enc_emb = (const float*)d_in[3];
    const float* enc_Wih = (const float*)d_in[4];
    const float* enc_Whh = (const float*)d_in[5];
    const float* enc_bih = (const float*)d_in[6];
    const float* enc_bhh = (const float*)d_in[7];
    const float* dec_emb = (const float*)d_in[8];
    const float* attn_W  = (const float*)d_in[9];
    const float* attn_b  = (const float*)d_in[10];
    const float* comb_W  = (const float*)d_in[11];
    const float* comb_b  = (const float*)d_in[12];
    const float* dec_Wih = (const float*)d_in[13];
    const float* dec_Whh = (const float*)d_in[14];
    const float* dec_bih = (const float*)d_in[15];
    const float* dec_bhh = (const float*)d_in[16];
    const float* out_W   = (const float*)d_in[17];
    const float* out_b   = (const float*)d_in[18];
    float* out = (float*)d_out;

    cudaFuncSetAttribute(gemm_f16, cudaFuncAttributeMaxDynamicSharedMemorySize, SMEM_F16);
    cudaFuncSetAttribute(x_gemm, cudaFuncAttributeMaxDynamicSharedMemorySize, SMEM_SX);

    float *p_h, *p_gh, *p_gi, *p_aw, *p_logits, *p_encpad, *p_PT;
    float *p_enc_tab, *p_attn_tab, *p_comb_tab, *p_scores, *p_cbias;
    __half *p_hsplit, *p_xsplit, *p_wenc, *p_wgi, *p_wcombo;
    cudaGetSymbolAddress((void**)&p_h, g_h);
    cudaGetSymbolAddress((void**)&p_gh, g_gh);
    cudaGetSymbolAddress((void**)&p_gi, g_gi);
    cudaGetSymbolAddress((void**)&p_aw, g_aw);
    cudaGetSymbolAddress((void**)&p_logits, g_logits);
    cudaGetSymbolAddress((void**)&p_encpad, g_encpad);
    cudaGetSymbolAddress((void**)&p_PT, g_PT);
    cudaGetSymbolAddress((void**)&p_enc_tab, g_enc_tab);
    cudaGetSymbolAddress((void**)&p_attn_tab, g_attn_tab);
    cudaGetSymbolAddress((void**)&p_comb_tab, g_comb_tab);
    cudaGetSymbolAddress((void**)&p_scores, g_scores);
    cudaGetSymbolAddress((void**)&p_cbias, g_combo_bias);
    cudaGetSymbolAddress((void**)&p_hsplit, g_hsplit);
    cudaGetSymbolAddress((void**)&p_xsplit, g_xsplit);
    cudaGetSymbolAddress((void**)&p_wenc, g_w_enc);
    cudaGetSymbolAddress((void**)&p_wgi, g_w_gi);
    cudaGetSymbolAddress((void**)&p_wcombo, g_w_combo);

    const int EW = (B * H + 255) / 256;
    const int GRU_GRID = (B * H / 2) / 256;

    // ---- prep ----
    init_h<<<EW, 256>>>(enc_h0);                                              // 0
    split_w<<<(H3 * 512 + 255) / 256, 256>>>(p_wenc, enc_Whh, H, 0, H3, 0);   // 1
    gemm_nt<<<dim3(24, 1), 256>>>(V, H3, H, enc_emb, H, enc_Wih, H,
                                  p_enc_tab, H3, enc_bih);                    // 2
    // encoder t=0,1 (launch 3 & 5 are gemm_f16 for ncu)
    launch_f16(dim3(24, 32), H3, p_hsplit, p_wenc, 0, p_gh, nullptr, enc_bhh,
               nullptr, nullptr, nullptr, 0);                                 // 3
    gru_gates<<<GRU_GRID, 256>>>(nullptr, p_enc_tab, input, p_gh, p_h,
                                 (__half2*)p_hsplit, p_encpad);               // 4
    launch_f16(dim3(24, 32), H3, p_hsplit, p_wenc, 0, p_gh, nullptr, enc_bhh,
               nullptr, nullptr, nullptr, 0);                                 // 5
    gru_gates<<<GRU_GRID, 256>>>(nullptr, p_enc_tab, input + B, p_gh, p_h,
                                 (__half2*)p_hsplit, p_encpad + H);

    // remaining prep
    split_w<<<(H3 * 512 + 255) / 256, 256>>>(p_wgi, dec_Wih, H, 0, H3, 0);
    split_w<<<(H3 * 512 + 255) / 256, 256>>>(p_wcombo, dec_Whh, H, 0, H3, 0);
    split_w<<<(V * 512 + 255) / 256, 256>>>(p_wcombo, out_W, H, 0, V, 1536);
    split_w<<<(L * 512 + 255) / 256, 256>>>(p_wcombo, attn_W, 2 * H, H, L, 1664);
    build_combo_bias<<<(NCOMBO + 255) / 256, 256>>>(dec_bhh, out_b);
    gemm_nt<<<dim3(1, 1), 256>>>(V, L, H, dec_emb, H, attn_W, 2 * H,
                                 p_attn_tab, L, attn_b);
    gemm_nt<<<dim3(8, 1), 256>>>(V, H, H, dec_emb, H, comb_W, 2 * H,
                                 p_comb_tab, H, comb_b);

    // ---- encoder t=2..40 ----
    for (int t = 2; t < L; t++) {
        launch_f16(dim3(24, 32), H3, p_hsplit, p_wenc, 0, p_gh, nullptr, enc_bhh,
                   nullptr, nullptr, nullptr, 0);
        gru_gates<<<GRU_GRID, 256>>>(nullptr, p_enc_tab, input + (size_t)t * B,
                                     p_gh, p_h, (__half2*)p_hsplit,
                                     p_encpad + (size_t)t * H);
    }

    // PT = comb_W[:, 512:] @ encpad^T
    gemm_nt<<<dim3(1, 4), 256>>>(H, L, H, comb_W + H, 2 * H,
                                 p_encpad, H, p_PT, 48, nullptr);

    // ---- decoder ----
    launch_f16(dim3(27, 32), NCOMBO, p_hsplit, p_wcombo, 1, p_gh, p_logits,
               p_cbias, p_attn_tab, nullptr, p_aw, 0);
    for (int t = 0; t < L; t++) {
        const int* tokPrev = (t == 0) ? nullptr : target + (size_t)(t - 1) * B;
        x_gemm<<<dim3(4, 32), 256, SMEM_SX>>>(p_aw, tokPrev, BOS, p_PT,
                                              p_comb_tab, p_xsplit);
        launch_f16(dim3(24, 32), H3, p_xsplit, p_wgi, 0, p_gi, nullptr, dec_bih,
                   nullptr, nullptr, nullptr, 0);
        gru_gates<<<GRU_GRID, 256>>>(p_gi, nullptr, nullptr, p_gh, p_h,
                                     (__half2*)p_hsplit, nullptr);
        if (t < L - 1) {
            launch_f16(dim3(27, 32), NCOMBO, p_hsplit, p_wcombo, 1, p_gh, p_logits,
                       p_cbias, p_attn_tab, target + (size_t)t * B, p_aw, 0);
        } else {
            launch_f16(dim3(2, 32), NCOMBO, p_hsplit, p_wcombo, 1, p_gh, p_logits,
                       p_cbias, p_attn_tab, target + (size_t)t * B, p_aw, 24);
        }
        out_gold<<<B / 8, 256>>>(p_logits, target + (size_t)t * B, p_scores);
    }

    // ---- outputs ----
    scores_out<<<16, 256>>>(out);
    bcast_out<<<dim3(21, B), 256>>>(out);
}

// round 14
// speedup vs baseline: 1.0675x; 1.0675x over previous
#include <cuda_runtime.h>
#include <cuda_fp16.h>
#include <math.h>
#include <stdint.h>

#define B 4096
#define H 512
#define H3 1536
#define L 41
#define V 128
#define BOS 2
#define KA 1024            /* A split: [Ah | Al] fp16 */
#define KW 1024            /* W split: [Wh | Wl] fp16 */
#define NCOMBO 1728        /* [gh 1536 | logits 128 | attn 41 pad-> 64] */

// ====================== device scratch ======================
__device__ __align__(128) float g_h[B * H];
__device__ __align__(128) float g_gh[B * H3];
__device__ __align__(128) float g_gi[B * H3];
__device__ __align__(128) float g_aw[B * 48];
__device__ __align__(128) float g_logits[2 * B * V];   /* double buffered */
__device__ __align__(128) float g_encpad[L * H];
__device__ __align__(128) float g_PT[H * 48];
__device__ __align__(128) float g_enc_tab[V * H3];
__device__ __align__(128) float g_attn_tab[V * L];
__device__ __align__(128) float g_comb_tab[V * H];
__device__ __align__(128) float g_scores[B];
__device__ __align__(128) float g_combo_bias[NCOMBO];

__device__ __align__(128) __half g_hsplit[B * KA];
__device__ __align__(128) __half g_xsplit[B * KA];
__device__ __align__(128) __half g_w_enc[H3 * KW];
__device__ __align__(128) __half g_w_gi[H3 * KW];
__device__ __align__(128) __half g_w_combo[NCOMBO * KW];

// ====================== asm helpers ======================
__device__ __forceinline__ uint32_t smem_u32(const void* p) {
    uint32_t a;
    asm("{ .reg .u64 t; cvta.to.shared.u64 t, %1; cvt.u32.u64 %0, t; }" : "=r"(a) : "l"(p));
    return a;
}
__device__ __forceinline__ void cp16(uint32_t s, const void* g) {
    asm volatile("cp.async.cg.shared.global [%0], [%1], 16;" :: "r"(s), "l"(g));
}
#define CP_COMMIT() asm volatile("cp.async.commit_group;" ::: "memory")
#define CP_WAIT1()  asm volatile("cp.async.wait_group 1;" ::: "memory")
#define CP_WAIT0()  asm volatile("cp.async.wait_group 0;" ::: "memory")
#define LDMX4(r0, r1, r2, r3, a) \
    asm volatile("ldmatrix.sync.aligned.m8n8.x4.shared.b16 {%0,%1,%2,%3}, [%4];" \
        : "=r"(r0), "=r"(r1), "=r"(r2), "=r"(r3) : "r"(a))
#define MMA16816(d, a, bb) \
    asm volatile("mma.sync.aligned.m16n8k16.row.col.f32.f16.f16.f32 " \
        "{%0,%1,%2,%3}, {%4,%5,%6,%7}, {%8,%9}, {%0,%1,%2,%3};" \
        : "+f"((d)[0]), "+f"((d)[1]), "+f"((d)[2]), "+f"((d)[3]) \
        : "r"((a)[0]), "r"((a)[1]), "r"((a)[2]), "r"((a)[3]), \
          "r"((bb)[0]), "r"((bb)[1]))

// ====================== fp16 3-segment HMMA GEMM (R11 config) ======================
// C = Ah*Wh + Ah*Wl + Al*Wh  (drops only Al*Wl ~2^-24), fp32 accum.
// BM=64, BN=64, 256 threads (8 warps 2m x 4n, warp tile 32x16), occ 3.
// Grid: (tiles_x, 64)  [64 row-blocks of 64 rows each].
// mode 0: C0[m*N+n] = acc + bias[n]
// mode 1 (combo, idx = blockIdx.x+tileOff, bn = idx*64):
//   idx == goldIdx   : NOT a GEMM tile — fused out_gold (64 rows) on goldLogits
//   bn<1536          : gh -> C0 (ld 1536, +bias)
//   1536<=bn<1664    : logits -> C2 (ld 128, +bias)
//   bn==1664         : attn(41) -> fused softmax (incl attn_tab[tok]) -> awOut
#define PITCH 144
#define TSEG (64 * PITCH)            /* 9216 */
#define OFF_WL TSEG
#define OFF_AH (2 * TSEG)
#define OFF_AL (3 * TSEG)
#define STAGE (4 * TSEG)             /* 36864 */
#define SMEM_F16 (2 * STAGE)         /* 73728 -> 3 CTAs / SM */

__global__ void __launch_bounds__(256, 3) gemm_f16(
    int N,
    const __half* __restrict__ A,
    const __half* __restrict__ W,
    int mode,
    float* __restrict__ C0,
    float* __restrict__ C2,
    const float* __restrict__ bias,
    const float* __restrict__ attn_tab,
    const int* __restrict__ tgt,
    float* __restrict__ awOut,
    int tileOff,
    int goldIdx,
    const float* __restrict__ goldLogits,
    const int* __restrict__ goldTgt,
    float* __restrict__ scores)
{
    extern __shared__ __align__(128) char smem[];
    const uint32_t sb = smem_u32(smem);
    const int tid = threadIdx.x;
    const int lane = tid & 31;
    const int wid = tid >> 5;
    const int idx = blockIdx.x + tileOff;

    // ---- fused out_gold CTA: 64 rows (8 warps x 8 rows) at blockIdx.y*64 ----
    if (mode == 1 && idx == goldIdx) {
        if (goldTgt != nullptr) {
#pragma unroll
            for (int rr = 0; rr < 8; rr++) {
                const size_t m = (size_t)blockIdx.y * 64 + wid * 8 + rr;
                const float* row = goldLogits + m * V;
                float x0 = row[lane];
                float x1 = row[lane + 32];
                float x2 = row[lane + 64];
                float x3 = row[lane + 96];
                float mx = fmaxf(fmaxf(x0, x1), fmaxf(x2, x3));
#pragma unroll
                for (int o = 16; o > 0; o >>= 1) mx = fmaxf(mx, __shfl_xor_sync(~0u, mx, o));
                float s = __expf(x0 - mx) + __expf(x1 - mx) + __expf(x2 - mx) + __expf(x3 - mx);
#pragma unroll
                for (int o = 16; o > 0; o >>= 1) s += __shfl_xor_sync(~0u, s, o);
                if (lane == 0) {
                    int tg = goldTgt[m];
                    if (tg != 0) scores[m] += row[tg] - (mx + logf(s));
                }
            }
        }
        return;
    }

    const int wm = wid >> 2;          // 0..1 -> 32 rows
    const int wn = wid & 3;           // 0..3 -> 16 cols
    const int bm = blockIdx.y * 64;
    const int bn = idx * 64;

    auto load_tile = [&](int c) {
        const uint32_t st = sb + (c & 1) * STAGE;
        const size_t koff = (size_t)c * 64;
#pragma unroll
        for (int i = 0; i < 2; i++) {
            int ii = tid + i * 256;           // 0..511 -> 64 rows x 8 cols
            int row = ii >> 3, col = ii & 7;
            const __half* wr = W + (size_t)(bn + row) * KW + koff + col * 8;
            cp16(st + row * PITCH + col * 16, wr);                 // Wh
            cp16(st + OFF_WL + row * PITCH + col * 16, wr + 512);  // Wl
            const __half* ar = A + (size_t)(bm + row) * KA + koff + col * 8;
            cp16(st + OFF_AH + row * PITCH + col * 16, ar);        // Ah
            cp16(st + OFF_AL + row * PITCH + col * 16, ar + 512);  // Al
        }
        CP_COMMIT();
    };

    float acc[2][2][4];
#pragma unroll
    for (int i = 0; i < 2; i++)
#pragma unroll
        for (int j = 0; j < 2; j++)
#pragma unroll
            for (int k = 0; k < 4; k++) acc[i][j][k] = 0.f;

    const uint32_t rowsel = lane & 15;
    const uint32_t khalf = (uint32_t)(lane >> 4);

    load_tile(0);
    load_tile(1);
    for (int c = 0; c < 8; c++) {
        if (c < 7) { CP_WAIT1(); }
        else       { CP_WAIT0(); }
        __syncthreads();

        const uint32_t st = sb + (c & 1) * STAGE;
        const uint32_t sWh = st + (wn * 16) * PITCH;
        const uint32_t sWl = st + OFF_WL + (wn * 16) * PITCH;
        const uint32_t sAh = st + OFF_AH + (wm * 32) * PITCH;
        const uint32_t sAl = st + OFF_AL + (wm * 32) * PITCH;
#pragma unroll
        for (int k16 = 0; k16 < 4; k16++) {
            const uint32_t kb = k16 * 32 + khalf * 16;
            uint32_t bh[2][2], bl[2][2];
            {
                uint32_t r0, r1, r2, r3;
                LDMX4(r0, r1, r2, r3, sWh + rowsel * PITCH + kb);
                bh[0][0] = r0; bh[1][0] = r1; bh[0][1] = r2; bh[1][1] = r3;
                LDMX4(r0, r1, r2, r3, sWl + rowsel * PITCH + kb);
                bl[0][0] = r0; bl[1][0] = r1; bl[0][1] = r2; bl[1][1] = r3;
            }
            uint32_t ah[2][4], al[2][4];
#pragma unroll
            for (int mi = 0; mi < 2; mi++) {
                LDMX4(ah[mi][0], ah[mi][1], ah[mi][2], ah[mi][3],
                      sAh + (mi * 16 + rowsel) * PITCH + kb);
                LDMX4(al[mi][0], al[mi][1], al[mi][2], al[mi][3],
                      sAl + (mi * 16 + rowsel) * PITCH + kb);
            }
#pragma unroll
            for (int mi = 0; mi < 2; mi++)
#pragma unroll
                for (int ni = 0; ni < 2; ni++)
                    MMA16816(acc[mi][ni], ah[mi], bh[ni]);
#pragma unroll
            for (int mi = 0; mi < 2; mi++)
#pragma unroll
                for (int ni = 0; ni < 2; ni++)
                    MMA16816(acc[mi][ni], ah[mi], bl[ni]);
#pragma unroll
            for (int mi = 0; mi < 2; mi++)
#pragma unroll
                for (int ni = 0; ni < 2; ni++)
                    MMA16816(acc[mi][ni], al[mi], bh[ni]);
        }
        __syncthreads();
        if (c + 2 < 8) load_tile(c + 2);
    }

    // ---- epilogue ----
    const int qr = lane >> 2;
    const int qc = (lane & 3) * 2;
    const bool fusedAttn = (mode == 1) && (bn == 1664);

    if (!fusedAttn) {
#pragma unroll
        for (int mi = 0; mi < 2; mi++) {
            const size_t m0 = (size_t)(bm + wm * 32 + mi * 16 + qr);
#pragma unroll
            for (int ni = 0; ni < 2; ni++) {
                const int n0 = bn + wn * 16 + ni * 8 + qc;
                float* a4 = acc[mi][ni];
                float v0 = a4[0] + bias[n0];
                float v1 = a4[1] + bias[n0 + 1];
                float v2 = a4[2] + bias[n0];
                float v3 = a4[3] + bias[n0 + 1];
                if (mode == 0) {
                    C0[m0 * N + n0]           = v0;
                    C0[m0 * N + n0 + 1]       = v1;
                    C0[(m0 + 8) * N + n0]     = v2;
                    C0[(m0 + 8) * N + n0 + 1] = v3;
                } else if (n0 < 1536) {
                    C0[m0 * 1536 + n0]           = v0;
                    C0[m0 * 1536 + n0 + 1]       = v1;
                    C0[(m0 + 8) * 1536 + n0]     = v2;
                    C0[(m0 + 8) * 1536 + n0 + 1] = v3;
                } else {
                    const int nl = n0 - 1536;
                    C2[m0 * 128 + nl]           = v0;
                    C2[m0 * 128 + nl + 1]       = v1;
                    C2[(m0 + 8) * 128 + nl]     = v2;
                    C2[(m0 + 8) * 128 + nl + 1] = v3;
                }
            }
        }
        return;
    }

    // fused attention softmax: stage 64x41 logits in smem
    float* ep = reinterpret_cast<float*>(smem);   // [64][49]
#pragma unroll
    for (int mi = 0; mi < 2; mi++) {
        const int r0 = wm * 32 + mi * 16 + qr;
#pragma unroll
        for (int ni = 0; ni < 2; ni++) {
            const int c0 = wn * 16 + ni * 8 + qc;
            float* a4 = acc[mi][ni];
#pragma unroll
            for (int e = 0; e < 4; e++) {
                const int r = r0 + ((e >= 2) ? 8 : 0);
                const int cc = c0 + (e & 1);
                if (cc < 41) ep[r * 49 + cc] = a4[e] + bias[bn + cc];
            }
        }
    }
    __syncthreads();

    if (tid < 64) {
        const size_t m = (size_t)(bm + tid);
        int tk = tgt ? tgt[m] : BOS;
        const float* tb = attn_tab + (size_t)tk * L;
        float* row = ep + tid * 49;
        float mx = -1e30f;
        for (int l = 0; l < L; l++) {
            float v = row[l] + tb[l];
            row[l] = v;
            mx = fmaxf(mx, v);
        }
        float s = 0.f;
        for (int l = 0; l < L; l++) {
            float e = __expf(row[l] - mx);
            row[l] = e;
            s += e;
        }
        float inv = 1.f / s;
        for (int l = 0; l < L; l++) row[l] *= inv;
        for (int l = L; l < 48; l++) row[l] = 0.f;
    }
    __syncthreads();
    for (int i = tid; i < 64 * 48; i += 256) {
        int r = i / 48, c = i - r * 48;
        awOut[(size_t)(bm + r) * 48 + c] = ep[r * 49 + c];
    }
}

// ====================== fp32 SIMT GEMM (prep tables + PT) ======================
__global__ void __launch_bounds__(256) gemm_nt(
    int M, int N, int K,
    const float* __restrict__ A, int lda,
    const float* __restrict__ W, int ldw,
    float* __restrict__ C, int ldc,
    const float* __restrict__ bias)
{
    __shared__ float As[16][128];
    __shared__ float Ws[16][64];
    const int bm = blockIdx.y * 128;
    const int bn = blockIdx.x * 64;
    const int tid = threadIdx.x;
    const int tx = tid & 15;
    const int ty = tid >> 4;

    float acc[8][4];
#pragma unroll
    for (int i = 0; i < 8; i++)
#pragma unroll
        for (int j = 0; j < 4; j++) acc[i][j] = 0.f;

    for (int k0 = 0; k0 < K; k0 += 16) {
#pragma unroll
        for (int i = 0; i < 2; i++) {
            int flat = tid + i * 256;
            int r = flat >> 2;
            int c4 = (flat & 3) << 2;
            float4 v = *reinterpret_cast<const float4*>(A + (size_t)(bm + r) * lda + k0 + c4);
            As[c4 + 0][r] = v.x; As[c4 + 1][r] = v.y;
            As[c4 + 2][r] = v.z; As[c4 + 3][r] = v.w;
        }
        {
            int r = tid >> 2;
            int c4 = (tid & 3) << 2;
            float4 v = make_float4(0.f, 0.f, 0.f, 0.f);
            if (bn + r < N)
                v = *reinterpret_cast<const float4*>(W + (size_t)(bn + r) * ldw + k0 + c4);
            Ws[c4 + 0][r] = v.x; Ws[c4 + 1][r] = v.y;
            Ws[c4 + 2][r] = v.z; Ws[c4 + 3][r] = v.w;
        }
        __syncthreads();
#pragma unroll
        for (int k = 0; k < 16; k++) {
            float4 a0 = *reinterpret_cast<const float4*>(&As[k][ty * 8]);
            float4 a1 = *reinterpret_cast<const float4*>(&As[k][ty * 8 + 4]);
            float4 w0 = *reinterpret_cast<const float4*>(&Ws[k][tx * 4]);
            float a[8] = {a0.x, a0.y, a0.z, a0.w, a1.x, a1.y, a1.z, a1.w};
            float w[4] = {w0.x, w0.y, w0.z, w0.w};
#pragma unroll
            for (int i = 0; i < 8; i++)
#pragma unroll
                for (int j = 0; j < 4; j++) acc[i][j] += a[i] * w[j];
        }
        __syncthreads();
    }

#pragma unroll
    for (int i = 0; i < 8; i++) {
        size_t m = (size_t)(bm + ty * 8 + i);
#pragma unroll
        for (int j = 0; j < 4; j++) {
            int n = bn + tx * 4 + j;
            if (n < N) {
                float v = acc[i][j];
                if (bias) v += bias[n];
                C[m * ldc + n] = v;
            }
        }
    }
}

// ====================== elementwise / fused small kernels ======================
__device__ __forceinline__ float sigmoidf_(float x) {
    return __fdividef(1.f, 1.f + __expf(-x));
}
__device__ __forceinline__ float tanhf_(float x) {
    return 1.f - __fdividef(2.f, __expf(2.f * x) + 1.f);
}

__global__ void gru_gates(const float* __restrict__ gi,
                          const float* __restrict__ giTab,
                          const int* __restrict__ tokRow,
                          const float* __restrict__ gh,
                          float* __restrict__ h,
                          __half2* __restrict__ hsplit,
                          float* __restrict__ encRow)
{
    int i = blockIdx.x * blockDim.x + threadIdx.x;   // < B*H/2
    int b = i >> 8;
    int j = (i & 255) << 1;
    const float* p;
    if (giTab) p = giTab + (size_t)tokRow[b] * H3;
    else       p = gi + (size_t)b * H3;
    float2 gir = *reinterpret_cast<const float2*>(p + j);
    float2 giz = *reinterpret_cast<const float2*>(p + H + j);
    float2 gin = *reinterpret_cast<const float2*>(p + 2 * H + j);
    const float* q = gh + (size_t)b * H3;
    float2 qr = *reinterpret_cast<const float2*>(q + j);
    float2 qz = *reinterpret_cast<const float2*>(q + H + j);
    float2 qn = *reinterpret_cast<const float2*>(q + 2 * H + j);
    float2 hv = *reinterpret_cast<const float2*>(h + (size_t)b * H + j);

    float r0 = sigmoidf_(gir.x + qr.x), r1 = sigmoidf_(gir.y + qr.y);
    float z0 = sigmoidf_(giz.x + qz.x), z1 = sigmoidf_(giz.y + qz.y);
    float n0 = tanhf_(gin.x + r0 * qn.x), n1 = tanhf_(gin.y + r1 * qn.y);
    float h0 = (1.f - z0) * n0 + z0 * hv.x;
    float h1 = (1.f - z1) * n1 + z1 * hv.y;

    *reinterpret_cast<float2*>(h + (size_t)b * H + j) = make_float2(h0, h1);
    __half hh0 = __float2half_rn(h0), hh1 = __float2half_rn(h1);
    __half hl0 = __float2half_rn(h0 - __half2float(hh0));
    __half hl1 = __float2half_rn(h1 - __half2float(hh1));
    size_t base = ((size_t)b * KA + j) >> 1;
    hsplit[base] = __halves2half2(hh0, hh1);
    hsplit[base + 256] = __halves2half2(hl0, hl1);
    if (encRow && b == 0)
        *reinterpret_cast<float2*>(encRow + j) = make_float2(h0, h1);
}

// x = relu(comb_tab[tok] + aw @ PT^T) + fp16 split; K=48 fp32
#define SXP 132
#define SMEM_SX (2 * 48 * SXP * 4 + 128 * 4)
__global__ void __launch_bounds__(256) x_gemm(
    const float* __restrict__ aw,
    const int* __restrict__ tok, int defTok,
    const float* __restrict__ PT,
    const float* __restrict__ comb_tab,
    __half* __restrict__ xsplit)
{
    extern __shared__ __align__(16) char smraw[];
    float* awT = reinterpret_cast<float*>(smraw);
    float* PTt = awT + 48 * SXP;
    int* toks = reinterpret_cast<int*>(PTt + 48 * SXP);
    const int tid = threadIdx.x;
    const int rb = blockIdx.y * 128;
    const int nb = blockIdx.x * 128;

#pragma unroll
    for (int i = 0; i < 6; i++) {
        int idx = tid + i * 256;
        int row = idx / 12, c4 = idx % 12;
        float4 v = *reinterpret_cast<const float4*>(PT + (size_t)(nb + row) * 48 + c4 * 4);
        PTt[(c4 * 4 + 0) * SXP + row] = v.x;
        PTt[(c4 * 4 + 1) * SXP + row] = v.y;
        PTt[(c4 * 4 + 2) * SXP + row] = v.z;
        PTt[(c4 * 4 + 3) * SXP + row] = v.w;
        float4 u = *reinterpret_cast<const float4*>(aw + (size_t)(rb + row) * 48 + c4 * 4);
        awT[(c4 * 4 + 0) * SXP + row] = u.x;
        awT[(c4 * 4 + 1) * SXP + row] = u.y;
        awT[(c4 * 4 + 2) * SXP + row] = u.z;
        awT[(c4 * 4 + 3) * SXP + row] = u.w;
    }
    if (tid < 128) toks[tid] = tok ? tok[rb + tid] : defTok;
    __syncthreads();

    const int ty = tid >> 4;
    const int tx = tid & 15;
    float acc[8][8];
#pragma unroll
    for (int i = 0; i < 8; i++)
#pragma unroll
        for (int j = 0; j < 8; j++) acc[i][j] = 0.f;

    for (int k = 0; k < 48; k++) {
        float4 a0 = *reinterpret_cast<const float4*>(awT + k * SXP + ty * 8);
        float4 a1 = *reinterpret_cast<const float4*>(awT + k * SXP + ty * 8 + 4);
        float4 b0 = *reinterpret_cast<const float4*>(PTt + k * SXP + tx * 8);
        float4 b1 = *reinterpret_cast<const float4*>(PTt + k * SXP + tx * 8 + 4);
        float a[8] = {a0.x, a0.y, a0.z, a0.w, a1.x, a1.y, a1.z, a1.w};
        float bb[8] = {b0.x, b0.y, b0.z, b0.w, b1.x, b1.y, b1.z, b1.w};
#pragma unroll
        for (int i = 0; i < 8; i++)
#pragma unroll
            for (int j = 0; j < 8; j++) acc[i][j] += a[i] * bb[j];
    }

#pragma unroll
    for (int i = 0; i < 8; i++) {
        size_t m = (size_t)(rb + ty * 8 + i);
        const float* tb = comb_tab + (size_t)toks[ty * 8 + i] * 512;
#pragma unroll
        for (int j = 0; j < 8; j++) {
            int n = nb + tx * 8 + j;
            float v = fmaxf(acc[i][j] + tb[n], 0.f);
            __half hi = __float2half_rn(v);
            __half lo = __float2half_rn(v - __half2float(hi));
            xsplit[m * KA + n] = hi;
            xsplit[m * KA + 512 + n] = lo;
        }
    }
}

__global__ void out_gold(const float* __restrict__ logits,
                         const int* __restrict__ tgtRow,
                         float* __restrict__ scores)
{
    int warp = (blockIdx.x * blockDim.x + threadIdx.x) >> 5;
    int lane = threadIdx.x & 31;
    if (warp >= B) return;
    const float* row = logits + (size_t)warp * V;
    float v[4];
    float mx = -1e30f;
#pragma unroll
    for (int i = 0; i < 4; i++) { v[i] = row[lane + 32 * i]; mx = fmaxf(mx, v[i]); }
#pragma unroll
    for (int o = 16; o > 0; o >>= 1) mx = fmaxf(mx, __shfl_xor_sync(~0u, mx, o));
    float s = 0.f;
#pragma unroll
    for (int i = 0; i < 4; i++) s += __expf(v[i] - mx);
#pragma unroll
    for (int o = 16; o > 0; o >>= 1) s += __shfl_xor_sync(~0u, s, o);
    if (lane == 0) {
        int tgt = tgtRow[warp];
        if (tgt != 0) scores[warp] += row[tgt] - (mx + logf(s));
    }
}

__global__ void init_h(const float* __restrict__ h0)
{
    int i = blockIdx.x * blockDim.x + threadIdx.x;
    if (i >= B * H) return;
    float v = h0[i];
    g_h[i] = v;
    int b = i >> 9, j = i & 511;
    __half hi = __float2half_rn(v);
    __half lo = __float2half_rn(v - __half2float(hi));
    size_t base = (size_t)b * KA + j;
    g_hsplit[base] = hi; g_hsplit[base + 512] = lo;
    if (i < B) g_scores[i] = 0.f;
}

__global__ void split_w(__half* __restrict__ dst,
                        const float* __restrict__ src, int ldw, int colOff,
                        int rows, int dstRowOff)
{
    int i = blockIdx.x * blockDim.x + threadIdx.x;
    if (i >= rows * 512) return;
    int r = i >> 9, k = i & 511;
    float w = src[(size_t)r * ldw + colOff + k];
    __half hi = __float2half_rn(w);
    __half lo = __float2half_rn(w - __half2float(hi));
    size_t base = (size_t)(dstRowOff + r) * KW + k;
    dst[base] = hi; dst[base + 512] = lo;
}

__global__ void build_combo_bias(const float* __restrict__ bhh,
                                 const float* __restrict__ outb)
{
    int n = blockIdx.x * blockDim.x + threadIdx.x;
    if (n >= NCOMBO) return;
    g_combo_bias[n] = (n < 1536) ? bhh[n] : ((n < 1664) ? outb[n - 1536] : 0.f);
}

__global__ void scores_out(float* __restrict__ out)
{
    int i = blockIdx.x * blockDim.x + threadIdx.x;
    if (i < B) out[i] = g_scores[i];
}

__global__ void bcast_out(float* __restrict__ out)
{
    int idx = blockIdx.x * 256 + threadIdx.x;
    if (idx >= (L * H) / 4) return;
    int b = blockIdx.y;
    const float4* src = reinterpret_cast<const float4*>(g_encpad);
    float4* dst = reinterpret_cast<float4*>(out) + (B / 4) + (size_t)b * (L * H / 4);
    dst[idx] = src[idx];
}

// ====================== host ======================
static void launch_f16(dim3 grid, int N, const __half* A, const __half* W, int mode,
                       float* C0, float* C2, const float* bias,
                       const float* attn_tab, const int* tgt, float* awOut,
                       int tileOff, int goldIdx, const float* goldLogits,
                       const int* goldTgt, float* scores)
{
    gemm_f16<<<grid, 256, SMEM_F16>>>(N, A, W, mode, C0, C2, bias, attn_tab,
                                      tgt, awOut, tileOff, goldIdx,
                                      goldLogits, goldTgt, scores);
}

extern "C" void kernel_launch(void* const* d_in, const int* in_sizes, int n_in,
                              void* d_out, int out_size)
{
    const int*   input   = (const int*)  d_in[0];
    const float* enc_h0  = (const float*)d_in[1];
    const int*   target  = (const int*)  d_in[2];
    const float* enc_emb = (const float*)d_in[3];
    const float* enc_Wih = (const float*)d_in[4];
    const float* enc_Whh = (const float*)d_in[5];
    const float* enc_bih = (const float*)d_in[6];
    const float* enc_bhh = (const float*)d_in[7];
    const float* dec_emb = (const float*)d_in[8];
    const float* attn_W  = (const float*)d_in[9];
    const float* attn_b  = (const float*)d_in[10];
    const float* comb_W  = (const float*)d_in[11];
    const float* comb_b  = (const float*)d_in[12];
    const float* dec_Wih = (const float*)d_in[13];
    const float* dec_Whh = (const float*)d_in[14];
    const float* dec_bih = (const float*)d_in[15];
    const float* dec_bhh = (const float*)d_in[16];
    const float* out_W   = (const float*)d_in[17];
    const float* out_b   = (const float*)d_in[18];
    float* out = (float*)d_out;

    cudaFuncSetAttribute(gemm_f16, cudaFuncAttributeMaxDynamicSharedMemorySize, SMEM_F16);
    cudaFuncSetAttribute(x_gemm, cudaFuncAttributeMaxDynamicSharedMemorySize, SMEM_SX);

    float *p_h, *p_gh, *p_gi, *p_aw, *p_logits, *p_encpad, *p_PT;
    float *p_enc_tab, *p_attn_tab, *p_comb_tab, *p_scores, *p_cbias;
    __half *p_hsplit, *p_xsplit, *p_wenc, *p_wgi, *p_wcombo;
    cudaGetSymbolAddress((void**)&p_h, g_h);
    cudaGetSymbolAddress((void**)&p_gh, g_gh);
    cudaGetSymbolAddress((void**)&p_gi, g_gi);
    cudaGetSymbolAddress((void**)&p_aw, g_aw);
    cudaGetSymbolAddress((void**)&p_logits, g_logits);
    cudaGetSymbolAddress((void**)&p_encpad, g_encpad);
    cudaGetSymbolAddress((void**)&p_PT, g_PT);
    cudaGetSymbolAddress((void**)&p_enc_tab, g_enc_tab);
    cudaGetSymbolAddress((void**)&p_attn_tab, g_attn_tab);
    cudaGetSymbolAddress((void**)&p_comb_tab, g_comb_tab);
    cudaGetSymbolAddress((void**)&p_scores, g_scores);
    cudaGetSymbolAddress((void**)&p_cbias, g_combo_bias);
    cudaGetSymbolAddress((void**)&p_hsplit, g_hsplit);
    cudaGetSymbolAddress((void**)&p_xsplit, g_xsplit);
    cudaGetSymbolAddress((void**)&p_wenc, g_w_enc);
    cudaGetSymbolAddress((void**)&p_wgi, g_w_gi);
    cudaGetSymbolAddress((void**)&p_wcombo, g_w_combo);

    float* pb0 = p_logits;
    float* pb1 = p_logits + (size_t)B * V;

    const int EW = (B * H + 255) / 256;
    const int GRU_GRID = (B * H / 2) / 256;

    // ---- prep ----
    init_h<<<EW, 256>>>(enc_h0);                                              // 0
    split_w<<<(H3 * 512 + 255) / 256, 256>>>(p_wenc, enc_Whh, H, 0, H3, 0);   // 1
    gemm_nt<<<dim3(24, 1), 256>>>(V, H3, H, enc_emb, H, enc_Wih, H,
                                  p_enc_tab, H3, enc_bih);                    // 2
    // encoder t=0,1 (launch 3 & 5 are gemm_f16 for ncu)
    launch_f16(dim3(24, 64), H3, p_hsplit, p_wenc, 0, p_gh, nullptr, enc_bhh,
               nullptr, nullptr, nullptr, 0, -1, nullptr, nullptr, nullptr);  // 3
    gru_gates<<<GRU_GRID, 256>>>(nullptr, p_enc_tab, input, p_gh, p_h,
                                 (__half2*)p_hsplit, p_encpad);               // 4
    launch_f16(dim3(24, 64), H3, p_hsplit, p_wenc, 0, p_gh, nullptr, enc_bhh,
               nullptr, nullptr, nullptr, 0, -1, nullptr, nullptr, nullptr);  // 5
    gru_gates<<<GRU_GRID, 256>>>(nullptr, p_enc_tab, input + B, p_gh, p_h,
                                 (__half2*)p_hsplit, p_encpad + H);

    // remaining prep
    split_w<<<(H3 * 512 + 255) / 256, 256>>>(p_wgi, dec_Wih, H, 0, H3, 0);
    split_w<<<(H3 * 512 + 255) / 256, 256>>>(p_wcombo, dec_Whh, H, 0, H3, 0);
    split_w<<<(V * 512 + 255) / 256, 256>>>(p_wcombo, out_W, H, 0, V, 1536);
    split_w<<<(L * 512 + 255) / 256, 256>>>(p_wcombo, attn_W, 2 * H, H, L, 1664);
    build_combo_bias<<<(NCOMBO + 255) / 256, 256>>>(dec_bhh, out_b);
    gemm_nt<<<dim3(1, 1), 256>>>(V, L, H, dec_emb, H, attn_W, 2 * H,
                                 p_attn_tab, L, attn_b);
    gemm_nt<<<dim3(8, 1), 256>>>(V, H, H, dec_emb, H, comb_W, 2 * H,
                                 p_comb_tab, H, comb_b);

    // ---- encoder t=2..40 ----
    for (int t = 2; t < L; t++) {
        launch_f16(dim3(24, 64), H3, p_hsplit, p_wenc, 0, p_gh, nullptr, enc_bhh,
                   nullptr, nullptr, nullptr, 0, -1, nullptr, nullptr, nullptr);
        gru_gates<<<GRU_GRID, 256>>>(nullptr, p_enc_tab, input + (size_t)t * B,
                                     p_gh, p_h, (__half2*)p_hsplit,
                                     p_encpad + (size_t)t * H);
    }

    // PT = comb_W[:, 512:] @ encpad^T
    gemm_nt<<<dim3(1, 4), 256>>>(H, L, H, comb_W + H, 2 * H,
                                 p_encpad, H, p_PT, 48, nullptr);

    // ---- decoder ----
    // preamble combo ("t=-1"): gh(0)+aw(0) from h_final; logits -> pb1 (unread); no gold
    launch_f16(dim3(27, 64), NCOMBO, p_hsplit, p_wcombo, 1, p_gh, pb1,
               p_cbias, p_attn_tab, nullptr, p_aw, 0, -1, nullptr, nullptr, nullptr);
    for (int t = 0; t < L; t++) {
        const int* tokPrev = (t == 0) ? nullptr : target + (size_t)(t - 1) * B;
        x_gemm<<<dim3(4, 32), 256, SMEM_SX>>>(p_aw, tokPrev, BOS, p_PT,
                                              p_comb_tab, p_xsplit);
        launch_f16(dim3(24, 64), H3, p_xsplit, p_wgi, 0, p_gi, nullptr, dec_bih,
                   nullptr, nullptr, nullptr, 0, -1, nullptr, nullptr, nullptr);
        gru_gates<<<GRU_GRID, 256>>>(p_gi, nullptr, nullptr, p_gh, p_h,
                                     (__half2*)p_hsplit, nullptr);
        float* curBuf  = (t & 1) ? pb1 : pb0;
        float* prevBuf = (t & 1) ? pb0 : pb1;
        if (t < L - 1) {
            // combo(t): 27 GEMM tiles + 1 fused-gold tile (idx 27) on logits(t-1)
            launch_f16(dim3(28, 64), NCOMBO, p_hsplit, p_wcombo, 1, p_gh, curBuf,
                       p_cbias, p_attn_tab, target + (size_t)t * B, p_aw, 0,
                       27, prevBuf, tokPrev, p_scores);
        } else {
            // t=40: logits tiles (idx 24,25) + fused-gold tile (idx 26) on logits(39)
            launch_f16(dim3(3, 64), NCOMBO, p_hsplit, p_wcombo, 1, p_gh, curBuf,
                       p_cbias, p_attn_tab, target + (size_t)t * B, p_aw, 24,
                       26, prevBuf, tokPrev, p_scores);
        }
    }
    // final gold: logits(40) live in pb0 (40 & 1 == 0)
    out_gold<<<B / 8, 256>>>(pb0, target + (size_t)(L - 1) * B, p_scores);

    // ---- outputs: [scores (B)] then [encoder_outputs (B, L, H)] ----
    scores_out<<<16, 256>>>(out);
    bcast_out<<<dim3(21, B), 256>>>(out);
}